// round 2
// baseline (speedup 1.0000x reference)
#include <cuda_runtime.h>
#include <cstdint>

// ---------------- problem constants ----------------
#define B_IMG 32
#define NSLOT 64          // B_IMG * TOPK
#define CIN   256
#define COUT  256
#define HIDC  512
#define HW    4096        // 64*64
#define NEXP  8
#define REDC  16

// ---------------- device scratch (no allocations allowed) ----------------
__device__ __align__(16) float g_Y1[(size_t)NSLOT * HIDC * HW];   // 512 MB
__device__ __align__(16) float g_Y2[(size_t)NSLOT * COUT * HW];   // 256 MB
__device__ __align__(16) float g_xd[B_IMG * CIN * 64];            // pooled 8x8
__device__ int   g_eidx[NSLOT];
__device__ float g_w[NSLOT];
__device__ float g_stat1[NSLOT * 8 * 2];   // per (slot, group): sum, sumsq
__device__ float g_stat2[NSLOT * 8 * 2];
__device__ float g_scale1[NSLOT * HIDC];
__device__ float g_shift1[NSLOT * HIDC];
__device__ float g_scale2[NSLOT * COUT];
__device__ float g_shift2[NSLOT * COUT];

// ---------------- small helpers ----------------
__device__ __forceinline__ float siluf(float a) {
    return a * (1.0f / (1.0f + __expf(-a)));
}
__device__ __forceinline__ void fma2(unsigned long long& c, unsigned long long a, unsigned long long b) {
    asm("fma.rn.f32x2 %0, %1, %2, %0;" : "+l"(c) : "l"(a), "l"(b));
}
__device__ __forceinline__ unsigned long long dup2(float x) {
    unsigned long long r;
    asm("mov.b64 %0, {%1, %1};" : "=l"(r) : "f"(x));
    return r;
}

// ---------------- kernel 0: zero the stat accumulators ----------------
__global__ void zero_stats_kernel() {
    int i = threadIdx.x;
    if (i < NSLOT * 8 * 2) { g_stat1[i] = 0.f; g_stat2[i] = 0.f; }
}

// ---------------- kernel 1: 8x8 average pool ----------------
// grid = B*C blocks, 256 threads; 4 threads cooperate per output bin.
__global__ void pool_kernel(const float* __restrict__ x) {
    int bc  = blockIdx.x;               // b*256 + c
    int tid = threadIdx.x;
    int bin = tid >> 2;                 // 0..63
    int q   = tid & 3;
    int i   = bin >> 3, j = bin & 7;
    const float* xp = x + (size_t)bc * HW;
    float s = 0.f;
#pragma unroll
    for (int rr = 0; rr < 2; rr++) {
        int row = i * 8 + q * 2 + rr;
        const float4* p = (const float4*)(xp + row * 64 + j * 8);
        float4 u = p[0], v = p[1];
        s += u.x + u.y + u.z + u.w + v.x + v.y + v.z + v.w;
    }
    s += __shfl_down_sync(0xffffffffu, s, 1);
    s += __shfl_down_sync(0xffffffffu, s, 2);
    if (q == 0) g_xd[bc * 64 + bin] = s * (1.f / 64.f);
}

// ---------------- kernel 2: router ----------------
// One block per image. dw3x3 -> GN(8)+SiLU -> 1x1(16) -> GN(4)+SiLU -> 1x1(8)
// -> softmax -> spatial mean -> top2 -> normalized, thresholded weights.
#define ROUTER_SMEM_FLOATS (16384 + 16384 + 1024 + 8)
__global__ void __launch_bounds__(256) router_kernel(
    const float* __restrict__ r_dw,
    const float* __restrict__ r_g1, const float* __restrict__ r_b1,
    const float* __restrict__ r_pw1,
    const float* __restrict__ r_g2, const float* __restrict__ r_b2,
    const float* __restrict__ r_pw2, const float* __restrict__ r_pb2)
{
    extern __shared__ float sm[];
    float* s_xd   = sm;            // 256*64
    float* s_h    = sm + 16384;    // 256*64
    float* s_h2   = sm + 32768;    // 16*64
    float* s_pool = sm + 33792;    // 8

    int b    = blockIdx.x;
    int tid  = threadIdx.x;
    int lane = tid & 31;
    int warp = tid >> 5;

    for (int i = tid; i < 16384; i += 256) s_xd[i] = g_xd[b * 16384 + i];
    if (tid < 8) s_pool[tid] = 0.f;
    __syncthreads();

    // depthwise 3x3 SAME on the 8x8 plane
    {
        int p = tid & 63, c0 = tid >> 6;
        int i = p >> 3, j = p & 7;
        for (int c = c0; c < 256; c += 4) {
            float acc = 0.f;
            const float* wd = r_dw + c * 9;
#pragma unroll
            for (int di = 0; di < 3; di++) {
                int ii = i + di - 1;
                if ((unsigned)ii < 8u) {
#pragma unroll
                    for (int dj = 0; dj < 3; dj++) {
                        int jj = j + dj - 1;
                        if ((unsigned)jj < 8u)
                            acc += s_xd[c * 64 + ii * 8 + jj] * wd[di * 3 + dj];
                    }
                }
            }
            s_h[c * 64 + p] = acc;
        }
    }
    __syncthreads();

    // GN(8 groups of 32ch x 64 spatial) + SiLU; warp g handles group g
    {
        int g = warp;
        float s = 0.f, ss = 0.f;
        for (int k = 0; k < 64; k++) {
            float v = s_h[g * 2048 + k * 32 + lane];
            s += v; ss += v * v;
        }
#pragma unroll
        for (int o = 16; o > 0; o >>= 1) {
            s  += __shfl_xor_sync(0xffffffffu, s, o);
            ss += __shfl_xor_sync(0xffffffffu, ss, o);
        }
        float mean = s * (1.f / 2048.f);
        float var  = ss * (1.f / 2048.f) - mean * mean;
        float inv  = rsqrtf(var + 1e-5f);
        for (int k = 0; k < 64; k++) {
            int el = k * 32 + lane;
            int ch = g * 32 + (el >> 6);
            float v = (s_h[g * 2048 + el] - mean) * inv;
            v = v * r_g1[ch] + r_b1[ch];
            s_h[g * 2048 + el] = siluf(v);
        }
    }
    __syncthreads();

    // 1x1: [16,256] @ s_h
    for (int o = tid; o < 1024; o += 256) {
        int r = o >> 6, p = o & 63;
        const float* wr = r_pw1 + r * 256;
        float acc = 0.f;
        for (int c = 0; c < 256; c++) acc += wr[c] * s_h[c * 64 + p];
        s_h2[o] = acc;
    }
    __syncthreads();

    // GN(4 groups of 4ch) + SiLU
    if (warp < 4) {
        int g = warp;
        float s = 0.f, ss = 0.f;
        for (int k = 0; k < 8; k++) {
            float v = s_h2[g * 256 + k * 32 + lane];
            s += v; ss += v * v;
        }
#pragma unroll
        for (int o = 16; o > 0; o >>= 1) {
            s  += __shfl_xor_sync(0xffffffffu, s, o);
            ss += __shfl_xor_sync(0xffffffffu, ss, o);
        }
        float mean = s * (1.f / 256.f);
        float var  = ss * (1.f / 256.f) - mean * mean;
        float inv  = rsqrtf(var + 1e-5f);
        for (int k = 0; k < 8; k++) {
            int el = k * 32 + lane;
            int ch = g * 4 + (el >> 6);
            float v = (s_h2[g * 256 + el] - mean) * inv;
            v = v * r_g2[ch] + r_b2[ch];
            s_h2[g * 256 + el] = siluf(v);
        }
    }
    __syncthreads();

    // logits + softmax per position, accumulate pooled
    if (tid < 64) {
        int p = tid;
        float l[8];
#pragma unroll
        for (int e = 0; e < 8; e++) {
            float acc = r_pb2[e];
#pragma unroll
            for (int r = 0; r < 16; r++) acc += r_pw2[e * 16 + r] * s_h2[r * 64 + p];
            l[e] = acc;
        }
        float mx = l[0];
#pragma unroll
        for (int e = 1; e < 8; e++) mx = fmaxf(mx, l[e]);
        float sum = 0.f;
#pragma unroll
        for (int e = 0; e < 8; e++) { l[e] = __expf(l[e] - mx); sum += l[e]; }
        float inv = 1.f / sum;
#pragma unroll
        for (int e = 0; e < 8; e++) atomicAdd(&s_pool[e], l[e] * inv);
    }
    __syncthreads();

    if (tid == 0) {
        float pooled[8];
#pragma unroll
        for (int e = 0; e < 8; e++) pooled[e] = s_pool[e] * (1.f / 64.f);
        int i1 = 0;
#pragma unroll
        for (int e = 1; e < 8; e++) if (pooled[e] > pooled[i1]) i1 = e;
        int i2 = (i1 == 0) ? 1 : 0;
#pragma unroll
        for (int e = 0; e < 8; e++) if (e != i1 && pooled[e] > pooled[i2]) i2 = e;
        float v1 = pooled[i1], v2 = pooled[i2];
        float s = v1 + v2 + 1e-9f;
        float w1 = v1 / s, w2 = v2 / s;
        if (!(w1 > 0.01f)) w1 = 0.f;
        if (!(w2 > 0.01f)) w2 = 0.f;
        g_eidx[2 * b]     = i1;
        g_eidx[2 * b + 1] = i2;
        g_w[2 * b]     = w1;
        g_w[2 * b + 1] = w2;
    }
}

// ---------------- GEMM: 128x128 tile, K-step 8, fp32 via fma.rn.f32x2 ----------------
// TR=false : Y1[n] = W1[e] (512x256) @ x[n/2] (256x4096), stats -> g_stat1
// TR=true  : Y2[n] = W2[e] (256x512) @ silu(gn1(Y1[n])) (512x4096), stats -> g_stat2
template<bool TR>
__global__ void __launch_bounds__(256, 2) gemm_kernel(
    const float* __restrict__ Wbase,
    const float* __restrict__ Xin,
    int M, int K, int grpM)
{
    __shared__ __align__(16) float As[2][8][128];
    __shared__ __align__(16) float Bs[2][8][128];
    __shared__ float s_sum[4], s_ss[4];

    int n   = blockIdx.z;
    if (g_w[n] == 0.f) return;      // thresholded-out slot: contributes exactly 0
    int bx  = blockIdx.x;   // col tile (HW/128)
    int by  = blockIdx.y;   // row tile (M/128)
    int tid = threadIdx.x;

    int e = g_eidx[n];
    const float* Wp = Wbase + (size_t)e * M * K;
    const float* Bp = TR ? (g_Y1 + (size_t)n * K * HW)
                         : (Xin + (size_t)(n >> 1) * K * HW);
    float* Cp    = (TR ? g_Y2 : g_Y1) + (size_t)n * M * HW;
    float* statp =  TR ? g_stat2 : g_stat1;

    int arow = tid >> 1;             // 0..127
    int acol = (tid & 1) * 4;        // 0 or 4
    int brow = tid >> 5;             // 0..7
    int bcol = (tid & 31) * 4;       // 0..124

    const float* Ap = Wp + (size_t)(by * 128 + arow) * K + acol;
    const float* Bg = Bp + (size_t)brow * HW + bx * 128 + bcol;

    auto loadB = [&](int kt) -> float4 {
        float4 v = *(const float4*)(Bg + (size_t)kt * 8 * HW);
        if (TR) {
            int kg = kt * 8 + brow;
            float sc = g_scale1[(size_t)n * K + kg];
            float sh = g_shift1[(size_t)n * K + kg];
            v.x = siluf(v.x * sc + sh);
            v.y = siluf(v.y * sc + sh);
            v.z = siluf(v.z * sc + sh);
            v.w = siluf(v.w * sc + sh);
        }
        return v;
    };

    // prologue: k-tile 0
    {
        float4 av = *(const float4*)Ap;
        float4 bv = loadB(0);
        As[0][acol + 0][arow] = av.x;
        As[0][acol + 1][arow] = av.y;
        As[0][acol + 2][arow] = av.z;
        As[0][acol + 3][arow] = av.w;
        *(float4*)&Bs[0][brow][bcol] = bv;
    }
    if (tid < 4) { s_sum[tid] = 0.f; s_ss[tid] = 0.f; }
    __syncthreads();

    unsigned long long acc[8][4];
#pragma unroll
    for (int i = 0; i < 8; i++)
#pragma unroll
        for (int j = 0; j < 4; j++) acc[i][j] = 0ULL;

    int ty = tid >> 4, tx = tid & 15;
    int nk = K >> 3;

    for (int kt = 0; kt < nk; kt++) {
        int cur = kt & 1;
        float4 av2, bv2;
        bool more = (kt + 1) < nk;
        if (more) {
            av2 = *(const float4*)(Ap + (kt + 1) * 8);
            bv2 = loadB(kt + 1);
        }
#pragma unroll
        for (int k = 0; k < 8; k++) {
            float4 a03 = *(const float4*)&As[cur][k][ty * 8];
            float4 a47 = *(const float4*)&As[cur][k][ty * 8 + 4];
            ulonglong2 b01 = *(const ulonglong2*)&Bs[cur][k][tx * 8];
            ulonglong2 b23 = *(const ulonglong2*)&Bs[cur][k][tx * 8 + 4];
            float aa[8] = {a03.x, a03.y, a03.z, a03.w, a47.x, a47.y, a47.z, a47.w};
#pragma unroll
            for (int i = 0; i < 8; i++) {
                unsigned long long ad = dup2(aa[i]);
                fma2(acc[i][0], ad, b01.x);
                fma2(acc[i][1], ad, b01.y);
                fma2(acc[i][2], ad, b23.x);
                fma2(acc[i][3], ad, b23.y);
            }
        }
        if (more) {
            int nxt = 1 - cur;
            As[nxt][acol + 0][arow] = av2.x;
            As[nxt][acol + 1][arow] = av2.y;
            As[nxt][acol + 2][arow] = av2.z;
            As[nxt][acol + 3][arow] = av2.w;
            *(float4*)&Bs[nxt][brow][bcol] = bv2;
        }
        __syncthreads();
    }

    // epilogue: write C, accumulate group stats
    float lsum = 0.f, lss = 0.f;
    int m0 = by * 128 + ty * 8;
    size_t cb = (size_t)bx * 128 + tx * 8;
#pragma unroll
    for (int i = 0; i < 8; i++) {
        union { unsigned long long u; float2 f; } c0, c1, c2, c3;
        c0.u = acc[i][0]; c1.u = acc[i][1]; c2.u = acc[i][2]; c3.u = acc[i][3];
        float4 o1 = make_float4(c0.f.x, c0.f.y, c1.f.x, c1.f.y);
        float4 o2 = make_float4(c2.f.x, c2.f.y, c3.f.x, c3.f.y);
        *(float4*)&Cp[(size_t)(m0 + i) * HW + cb]     = o1;
        *(float4*)&Cp[(size_t)(m0 + i) * HW + cb + 4] = o2;
        lsum += o1.x + o1.y + o1.z + o1.w + o2.x + o2.y + o2.z + o2.w;
        lss  += o1.x*o1.x + o1.y*o1.y + o1.z*o1.z + o1.w*o1.w
              + o2.x*o2.x + o2.y*o2.y + o2.z*o2.z + o2.w*o2.w;
    }
    int gl = (ty * 8) / grpM;           // all 8 rows of this thread share a group
    atomicAdd(&s_sum[gl], lsum);
    atomicAdd(&s_ss[gl], lss);
    __syncthreads();
    int ngrp = 128 / grpM;
    if (tid < ngrp) {
        int gg = (by * 128) / grpM + tid;
        atomicAdd(&statp[((size_t)n * 8 + gg) * 2],     s_sum[tid]);
        atomicAdd(&statp[((size_t)n * 8 + gg) * 2 + 1], s_ss[tid]);
    }
}

// ---------------- finalize GN1 -> per-channel scale/shift ----------------
__global__ void finalize1_kernel(const float* __restrict__ e_g1,
                                 const float* __restrict__ e_b1) {
    int n = blockIdx.x;
    int c = threadIdx.x;           // 0..511
    if (g_w[n] == 0.f) {           // skipped slot: keep pipeline NaN-free
        g_scale1[n * HIDC + c] = 0.f;
        g_shift1[n * HIDC + c] = 0.f;
        return;
    }
    int e = g_eidx[n];
    int g = c >> 6;                // 64 ch / group
    float cnt = 64.f * 4096.f;
    float s  = g_stat1[(n * 8 + g) * 2];
    float ss = g_stat1[(n * 8 + g) * 2 + 1];
    float mean = s / cnt;
    float var  = ss / cnt - mean * mean;
    float inv  = rsqrtf(var + 1e-5f);
    float gm = e_g1[e * HIDC + c], bt = e_b1[e * HIDC + c];
    g_scale1[n * HIDC + c] = inv * gm;
    g_shift1[n * HIDC + c] = bt - mean * inv * gm;
}

// ---------------- finalize GN2 (+ routing weight folded in) ----------------
__global__ void finalize2_kernel(const float* __restrict__ e_g2,
                                 const float* __restrict__ e_b2) {
    int n = blockIdx.x;
    int c = threadIdx.x;           // 0..255
    float w = g_w[n];
    if (w == 0.f) {                // skipped slot contributes exactly 0
        g_scale2[n * COUT + c] = 0.f;
        g_shift2[n * COUT + c] = 0.f;
        return;
    }
    int e = g_eidx[n];
    int g = c >> 5;                // 32 ch / group
    float cnt = 32.f * 4096.f;
    float s  = g_stat2[(n * 8 + g) * 2];
    float ss = g_stat2[(n * 8 + g) * 2 + 1];
    float mean = s / cnt;
    float var  = ss / cnt - mean * mean;
    float inv  = rsqrtf(var + 1e-5f);
    float gm = e_g2[e * COUT + c], bt = e_b2[e * COUT + c];
    g_scale2[n * COUT + c] = w * inv * gm;
    g_shift2[n * COUT + c] = w * (bt - mean * inv * gm);
}

// ---------------- combine the two slots per image ----------------
// Note: if a slot was skipped (w==0), its scale2/shift2 are 0, so its (stale
// but finite) g_Y2 contents are multiplied by exactly 0.
__global__ void combine_kernel(float* __restrict__ out) {
    size_t i = (size_t)blockIdx.x * 256 + threadIdx.x;   // float4 units
    if (i >= (size_t)B_IMG * COUT * (HW / 4)) return;
    int p4 = (int)(i & 1023);
    int c  = (int)((i >> 10) & 255);
    int b  = (int)(i >> 18);
    int n0 = 2 * b;
    float S0 = g_scale2[n0 * COUT + c],       T0 = g_shift2[n0 * COUT + c];
    float S1 = g_scale2[(n0 + 1) * COUT + c], T1 = g_shift2[(n0 + 1) * COUT + c];
    const float4 y0 = *(const float4*)&g_Y2[((size_t)n0 * COUT + c) * HW + p4 * 4];
    const float4 y1 = *(const float4*)&g_Y2[((size_t)(n0 + 1) * COUT + c) * HW + p4 * 4];
    float T = T0 + T1;
    float4 o;
    o.x = y0.x * S0 + y1.x * S1 + T;
    o.y = y0.y * S0 + y1.y * S1 + T;
    o.z = y0.z * S0 + y1.z * S1 + T;
    o.w = y0.w * S0 + y1.w * S1 + T;
    *(float4*)&out[i * 4] = o;
}

// ---------------- launch ----------------
extern "C" void kernel_launch(void* const* d_in, const int* in_sizes, int n_in,
                              void* d_out, int out_size) {
    const float* x     = (const float*)d_in[0];
    const float* r_dw  = (const float*)d_in[1];
    const float* r_g1  = (const float*)d_in[2];
    const float* r_b1  = (const float*)d_in[3];
    const float* r_pw1 = (const float*)d_in[4];
    const float* r_g2  = (const float*)d_in[5];
    const float* r_b2  = (const float*)d_in[6];
    const float* r_pw2 = (const float*)d_in[7];
    const float* r_pb2 = (const float*)d_in[8];
    const float* e_w1  = (const float*)d_in[9];
    const float* e_g1  = (const float*)d_in[10];
    const float* e_b1  = (const float*)d_in[11];
    const float* e_w2  = (const float*)d_in[12];
    const float* e_g2  = (const float*)d_in[13];
    const float* e_b2  = (const float*)d_in[14];
    float* out = (float*)d_out;

    const int router_smem = ROUTER_SMEM_FLOATS * (int)sizeof(float);
    cudaFuncSetAttribute(router_kernel, cudaFuncAttributeMaxDynamicSharedMemorySize, router_smem);

    zero_stats_kernel<<<1, 1024>>>();
    pool_kernel<<<B_IMG * CIN, 256>>>(x);
    router_kernel<<<B_IMG, 256, router_smem>>>(r_dw, r_g1, r_b1, r_pw1, r_g2, r_b2, r_pw2, r_pb2);
    gemm_kernel<false><<<dim3(HW / 128, HIDC / 128, NSLOT), 256>>>(e_w1, x, HIDC, CIN, 64);
    finalize1_kernel<<<NSLOT, HIDC>>>(e_g1, e_b1);
    gemm_kernel<true><<<dim3(HW / 128, COUT / 128, NSLOT), 256>>>(e_w2, x, COUT, HIDC, 32);
    finalize2_kernel<<<NSLOT, COUT>>>(e_g2, e_b2);
    combine_kernel<<<(B_IMG * COUT * (HW / 4) + 255) / 256, 256>>>(out);
}

// round 7
// speedup vs baseline: 1.8666x; 1.8666x over previous
#include <cuda_runtime.h>
#include <cuda_bf16.h>
#include <cstdint>

// ---------------- problem constants ----------------
#define B_IMG 32
#define NSLOT 64          // B_IMG * TOPK
#define CIN   256
#define COUT  256
#define HIDC  512
#define HW    4096        // 64*64
#define NEXP  8

// ---------------- device scratch (no allocations allowed) ----------------
__device__ __align__(16) float g_Y1[(size_t)NSLOT * HW * HIDC];   // Y1T: [slot][s][hid]
__device__ __align__(16) float g_Y2[(size_t)NSLOT * COUT * HW];   // [slot][c][s]
__device__ __align__(16) float g_xT[(size_t)B_IMG * HW * CIN];    // [b][s][c]
__device__ __align__(16) __nv_bfloat16 g_w1hi[NEXP * HIDC * CIN];
__device__ __align__(16) __nv_bfloat16 g_w1lo[NEXP * HIDC * CIN];
__device__ __align__(16) __nv_bfloat16 g_w2hi[NEXP * COUT * HIDC];
__device__ __align__(16) __nv_bfloat16 g_w2lo[NEXP * COUT * HIDC];
__device__ __align__(16) float g_xd[B_IMG * CIN * 64];
__device__ int   g_eidx[NSLOT];
__device__ float g_w[NSLOT];
__device__ float g_stat1[NSLOT * 8 * 2];
__device__ float g_stat2[NSLOT * 8 * 2];
__device__ float g_scale1[NSLOT * HIDC];
__device__ float g_shift1[NSLOT * HIDC];
__device__ float g_scale2[NSLOT * COUT];
__device__ float g_shift2[NSLOT * COUT];

// ---------------- helpers ----------------
__device__ __forceinline__ float siluf(float a) { return a * (1.0f / (1.0f + __expf(-a))); }
__device__ __forceinline__ uint32_t pk2(__nv_bfloat16 a, __nv_bfloat16 b) {
    __nv_bfloat162 t; t.x = a; t.y = b;
    return *reinterpret_cast<uint32_t*>(&t);
}
// m16n8k16 row.col bf16 MMA, fp32 accumulate (sm_80+ PTX, compiles at compute_100)
__device__ __forceinline__ void mma16816(float* d,
                                         uint32_t a0, uint32_t a1, uint32_t a2, uint32_t a3,
                                         uint32_t b0, uint32_t b1) {
    asm volatile(
        "mma.sync.aligned.m16n8k16.row.col.f32.bf16.bf16.f32 "
        "{%0,%1,%2,%3}, {%4,%5,%6,%7}, {%8,%9}, {%0,%1,%2,%3};"
        : "+f"(d[0]), "+f"(d[1]), "+f"(d[2]), "+f"(d[3])
        : "r"(a0), "r"(a1), "r"(a2), "r"(a3), "r"(b0), "r"(b1));
}

// ---------------- kernel: zero stats ----------------
__global__ void zero_stats_kernel() {
    int i = threadIdx.x;
    if (i < NSLOT * 8 * 2) { g_stat1[i] = 0.f; g_stat2[i] = 0.f; }
}

// ---------------- kernel: split weights to bf16 hi/lo ----------------
__global__ void preconv_kernel(const float* __restrict__ w1, const float* __restrict__ w2) {
    int i = blockIdx.x * 256 + threadIdx.x;
    const int N1 = NEXP * HIDC * CIN;
    const int N2 = NEXP * COUT * HIDC;
    if (i < N1) {
        float v = w1[i];
        __nv_bfloat16 h = __float2bfloat16(v);
        g_w1hi[i] = h;
        g_w1lo[i] = __float2bfloat16(v - __bfloat162float(h));
    } else if (i < N1 + N2) {
        int j = i - N1;
        float v = w2[j];
        __nv_bfloat16 h = __float2bfloat16(v);
        g_w2hi[j] = h;
        g_w2lo[j] = __float2bfloat16(v - __bfloat162float(h));
    }
}

// ---------------- kernel: transpose x -> xT [b][s][c] ----------------
__global__ void transpose_kernel(const float* __restrict__ x) {
    __shared__ float t[32][33];
    int b = blockIdx.z;
    int s0 = blockIdx.x * 32, c0 = blockIdx.y * 32;
    int tx = threadIdx.x, ty = threadIdx.y;   // 32 x 8
    const float* xp = x + (size_t)b * CIN * HW;
#pragma unroll
    for (int i = 0; i < 4; i++)
        t[ty + i * 8][tx] = xp[(size_t)(c0 + ty + i * 8) * HW + s0 + tx];
    __syncthreads();
    float* o = g_xT + (size_t)b * HW * CIN;
#pragma unroll
    for (int i = 0; i < 4; i++)
        o[(size_t)(s0 + ty + i * 8) * CIN + c0 + tx] = t[tx][ty + i * 8];
}

// ---------------- kernel: 8x8 average pool ----------------
__global__ void pool_kernel(const float* __restrict__ x) {
    int bc  = blockIdx.x;
    int tid = threadIdx.x;
    int bin = tid >> 2;
    int q   = tid & 3;
    int i   = bin >> 3, j = bin & 7;
    const float* xp = x + (size_t)bc * HW;
    float s = 0.f;
#pragma unroll
    for (int rr = 0; rr < 2; rr++) {
        int row = i * 8 + q * 2 + rr;
        const float4* p = (const float4*)(xp + row * 64 + j * 8);
        float4 u = p[0], v = p[1];
        s += u.x + u.y + u.z + u.w + v.x + v.y + v.z + v.w;
    }
    s += __shfl_down_sync(0xffffffffu, s, 1);
    s += __shfl_down_sync(0xffffffffu, s, 2);
    if (q == 0) g_xd[bc * 64 + bin] = s * (1.f / 64.f);
}

// ---------------- kernel: router ----------------
#define ROUTER_SMEM_FLOATS (16384 + 16384 + 1024 + 8)
__global__ void __launch_bounds__(256) router_kernel(
    const float* __restrict__ r_dw,
    const float* __restrict__ r_g1, const float* __restrict__ r_b1,
    const float* __restrict__ r_pw1,
    const float* __restrict__ r_g2, const float* __restrict__ r_b2,
    const float* __restrict__ r_pw2, const float* __restrict__ r_pb2)
{
    extern __shared__ float sm[];
    float* s_xd   = sm;
    float* s_h    = sm + 16384;
    float* s_h2   = sm + 32768;
    float* s_pool = sm + 33792;

    int b    = blockIdx.x;
    int tid  = threadIdx.x;
    int lane = tid & 31;
    int warp = tid >> 5;

    for (int i = tid; i < 16384; i += 256) s_xd[i] = g_xd[b * 16384 + i];
    if (tid < 8) s_pool[tid] = 0.f;
    __syncthreads();

    {
        int p = tid & 63, c0 = tid >> 6;
        int i = p >> 3, j = p & 7;
        for (int c = c0; c < 256; c += 4) {
            float acc = 0.f;
            const float* wd = r_dw + c * 9;
#pragma unroll
            for (int di = 0; di < 3; di++) {
                int ii = i + di - 1;
                if ((unsigned)ii < 8u) {
#pragma unroll
                    for (int dj = 0; dj < 3; dj++) {
                        int jj = j + dj - 1;
                        if ((unsigned)jj < 8u)
                            acc += s_xd[c * 64 + ii * 8 + jj] * wd[di * 3 + dj];
                    }
                }
            }
            s_h[c * 64 + p] = acc;
        }
    }
    __syncthreads();

    {
        int g = warp;
        float s = 0.f, ss = 0.f;
        for (int k = 0; k < 64; k++) {
            float v = s_h[g * 2048 + k * 32 + lane];
            s += v; ss += v * v;
        }
#pragma unroll
        for (int o = 16; o > 0; o >>= 1) {
            s  += __shfl_xor_sync(0xffffffffu, s, o);
            ss += __shfl_xor_sync(0xffffffffu, ss, o);
        }
        float mean = s * (1.f / 2048.f);
        float var  = ss * (1.f / 2048.f) - mean * mean;
        float inv  = rsqrtf(var + 1e-5f);
        for (int k = 0; k < 64; k++) {
            int el = k * 32 + lane;
            int ch = g * 32 + (el >> 6);
            float v = (s_h[g * 2048 + el] - mean) * inv;
            v = v * r_g1[ch] + r_b1[ch];
            s_h[g * 2048 + el] = siluf(v);
        }
    }
    __syncthreads();

    for (int o = tid; o < 1024; o += 256) {
        int r = o >> 6, p = o & 63;
        const float* wr = r_pw1 + r * 256;
        float acc = 0.f;
        for (int c = 0; c < 256; c++) acc += wr[c] * s_h[c * 64 + p];
        s_h2[o] = acc;
    }
    __syncthreads();

    if (warp < 4) {
        int g = warp;
        float s = 0.f, ss = 0.f;
        for (int k = 0; k < 8; k++) {
            float v = s_h2[g * 256 + k * 32 + lane];
            s += v; ss += v * v;
        }
#pragma unroll
        for (int o = 16; o > 0; o >>= 1) {
            s  += __shfl_xor_sync(0xffffffffu, s, o);
            ss += __shfl_xor_sync(0xffffffffu, ss, o);
        }
        float mean = s * (1.f / 256.f);
        float var  = ss * (1.f / 256.f) - mean * mean;
        float inv  = rsqrtf(var + 1e-5f);
        for (int k = 0; k < 8; k++) {
            int el = k * 32 + lane;
            int ch = g * 4 + (el >> 6);
            float v = (s_h2[g * 256 + el] - mean) * inv;
            v = v * r_g2[ch] + r_b2[ch];
            s_h2[g * 256 + el] = siluf(v);
        }
    }
    __syncthreads();

    if (tid < 64) {
        int p = tid;
        float l[8];
#pragma unroll
        for (int e = 0; e < 8; e++) {
            float acc = r_pb2[e];
#pragma unroll
            for (int r = 0; r < 16; r++) acc += r_pw2[e * 16 + r] * s_h2[r * 64 + p];
            l[e] = acc;
        }
        float mx = l[0];
#pragma unroll
        for (int e = 1; e < 8; e++) mx = fmaxf(mx, l[e]);
        float sum = 0.f;
#pragma unroll
        for (int e = 0; e < 8; e++) { l[e] = __expf(l[e] - mx); sum += l[e]; }
        float inv = 1.f / sum;
#pragma unroll
        for (int e = 0; e < 8; e++) atomicAdd(&s_pool[e], l[e] * inv);
    }
    __syncthreads();

    if (tid == 0) {
        float pooled[8];
#pragma unroll
        for (int e = 0; e < 8; e++) pooled[e] = s_pool[e] * (1.f / 64.f);
        int i1 = 0;
#pragma unroll
        for (int e = 1; e < 8; e++) if (pooled[e] > pooled[i1]) i1 = e;
        int i2 = (i1 == 0) ? 1 : 0;
#pragma unroll
        for (int e = 0; e < 8; e++) if (e != i1 && pooled[e] > pooled[i2]) i2 = e;
        float v1 = pooled[i1], v2 = pooled[i2];
        float s = v1 + v2 + 1e-9f;
        float w1 = v1 / s, w2 = v2 / s;
        if (!(w1 > 0.01f)) w1 = 0.f;
        if (!(w2 > 0.01f)) w2 = 0.f;
        g_eidx[2 * b]     = i1;
        g_eidx[2 * b + 1] = i2;
        g_w[2 * b]     = w1;
        g_w[2 * b + 1] = w2;
    }
}

// ---------------- HMMA split-bf16 GEMM (mma.sync m16n8k16) ----------------
// TR=false: Y1T[slot][s][hid] = W1[e](512x256) @ xT[img](4096x256 K-major), stats1
// TR=true : Y2[slot][c][s]    = W2[e](256x512) @ silu(gn1(Y1T))(4096x512 K-major), stats2
// CTA = 128(M) x 128(N=spatial). 8 warps as 4(M)x2(N); warp = 32x64.
// K chunks of 64. Split-bf16: acc += Ahi*Bhi + Ahi*Blo + Alo*Bhi.
// SMEM rows padded to 72 halves (144B) -> conflict-free fragment LDS.
#define PAD_ROW   144                     // bytes per 64-half row (64*2 + 16 pad)
#define TILE_SZ   (128 * PAD_ROW)         // 18432
#define OFF_ALO   TILE_SZ
#define OFF_BHI   (2 * TILE_SZ)
#define OFF_BLO   (3 * TILE_SZ)
#define GEMM_SMEM (4 * TILE_SZ)           // 73728

template<bool TR>
__global__ __launch_bounds__(256, 2)
void hmma_gemm_kernel()
{
    constexpr int M  = TR ? COUT : HIDC;
    constexpr int K  = TR ? HIDC : CIN;
    constexpr int NC = K / 64;

    extern __shared__ __align__(16) char smc[];
    const int n = blockIdx.z;
    if (g_w[n] == 0.f) return;
    const int bx = blockIdx.x, by = blockIdx.y;
    const int tid = threadIdx.x, lane = tid & 31, wid = tid >> 5;
    const int m0 = by * 128, s0 = bx * 128;
    const int e = g_eidx[n];

    const __nv_bfloat16* Whi = TR ? g_w2hi : g_w1hi;
    const __nv_bfloat16* Wlo = TR ? g_w2lo : g_w1lo;
    const float* bsrc = TR ? (g_Y1 + (size_t)n * HW * HIDC)
                           : (g_xT + (size_t)(n >> 1) * HW * CIN);
    const float* scp = g_scale1 + (size_t)n * HIDC;
    const float* shp = g_shift1 + (size_t)n * HIDC;

    const int row = tid >> 1, hk = tid & 1;            // loader mapping
    const size_t aRow = ((size_t)e * M + m0 + row) * K;
    const size_t bRow = (size_t)(s0 + row) * K;

    const int g = lane >> 2, t = lane & 3;             // fragment mapping
    const int warp_m = wid & 3, warp_n = wid >> 2;
    const int aOff = (warp_m * 32 + g) * PAD_ROW + t * 4;
    const int bOff = (warp_n * 64 + g) * PAD_ROW + t * 4;

    float acc[2][8][4];
#pragma unroll
    for (int mt = 0; mt < 2; mt++)
#pragma unroll
        for (int nt = 0; nt < 8; nt++)
#pragma unroll
            for (int q = 0; q < 4; q++) acc[mt][nt][q] = 0.f;

    for (int c = 0; c < NC; c++) {
        const int k0 = c * 64;
        __syncthreads();          // previous compute done before overwrite
        // ---- A tiles (preconverted bf16 hi/lo), rows = M, 64 halves ----
#pragma unroll
        for (int i = 0; i < 4; i++) {
            int u = hk * 4 + i;                       // 8-half chunk index
            uint4 h = *(const uint4*)(Whi + aRow + k0 + u * 8);
            uint4 l = *(const uint4*)(Wlo + aRow + k0 + u * 8);
            *(uint4*)(smc + row * PAD_ROW + u * 16)           = h;
            *(uint4*)(smc + OFF_ALO + row * PAD_ROW + u * 16) = l;
        }
        // ---- B tiles (fp32 load, optional GN1+SiLU, hi/lo split) ----
#pragma unroll
        for (int i = 0; i < 4; i++) {
            int j0 = hk * 32 + i * 8;
            float4 v0 = *(const float4*)(bsrc + bRow + k0 + j0);
            float4 v1 = *(const float4*)(bsrc + bRow + k0 + j0 + 4);
            if (TR) {
                float4 sc0 = *(const float4*)(scp + k0 + j0);
                float4 sh0 = *(const float4*)(shp + k0 + j0);
                float4 sc1 = *(const float4*)(scp + k0 + j0 + 4);
                float4 sh1 = *(const float4*)(shp + k0 + j0 + 4);
                v0.x = siluf(fmaf(v0.x, sc0.x, sh0.x));
                v0.y = siluf(fmaf(v0.y, sc0.y, sh0.y));
                v0.z = siluf(fmaf(v0.z, sc0.z, sh0.z));
                v0.w = siluf(fmaf(v0.w, sc0.w, sh0.w));
                v1.x = siluf(fmaf(v1.x, sc1.x, sh1.x));
                v1.y = siluf(fmaf(v1.y, sc1.y, sh1.y));
                v1.z = siluf(fmaf(v1.z, sc1.z, sh1.z));
                v1.w = siluf(fmaf(v1.w, sc1.w, sh1.w));
            }
            float f[8] = {v0.x, v0.y, v0.z, v0.w, v1.x, v1.y, v1.z, v1.w};
            uint4 hi, lo;
            uint32_t* hp = (uint32_t*)&hi;
            uint32_t* lp = (uint32_t*)&lo;
#pragma unroll
            for (int q = 0; q < 4; q++) {
                float a = f[2 * q], b2 = f[2 * q + 1];
                __nv_bfloat16 ha = __float2bfloat16(a), hb = __float2bfloat16(b2);
                hp[q] = pk2(ha, hb);
                lp[q] = pk2(__float2bfloat16(a  - __bfloat162float(ha)),
                            __float2bfloat16(b2 - __bfloat162float(hb)));
            }
            *(uint4*)(smc + OFF_BHI + row * PAD_ROW + j0 * 2) = hi;
            *(uint4*)(smc + OFF_BLO + row * PAD_ROW + j0 * 2) = lo;
        }
        __syncthreads();
        // ---- compute: 4 k16-steps per chunk ----
#pragma unroll
        for (int ks = 0; ks < 4; ks++) {
            const int ka = ks * 32;                   // k0*2 bytes
            uint32_t ah[2][4], al[2][4];
#pragma unroll
            for (int mt = 0; mt < 2; mt++) {
                int ab = aOff + mt * (16 * PAD_ROW) + ka;
                ah[mt][0] = *(const uint32_t*)(smc + ab);
                ah[mt][1] = *(const uint32_t*)(smc + ab + 8 * PAD_ROW);
                ah[mt][2] = *(const uint32_t*)(smc + ab + 16);
                ah[mt][3] = *(const uint32_t*)(smc + ab + 8 * PAD_ROW + 16);
                al[mt][0] = *(const uint32_t*)(smc + OFF_ALO + ab);
                al[mt][1] = *(const uint32_t*)(smc + OFF_ALO + ab + 8 * PAD_ROW);
                al[mt][2] = *(const uint32_t*)(smc + OFF_ALO + ab + 16);
                al[mt][3] = *(const uint32_t*)(smc + OFF_ALO + ab + 8 * PAD_ROW + 16);
            }
#pragma unroll
            for (int nt = 0; nt < 8; nt++) {
                int bb = bOff + nt * (8 * PAD_ROW) + ka;
                uint32_t bh0 = *(const uint32_t*)(smc + OFF_BHI + bb);
                uint32_t bh1 = *(const uint32_t*)(smc + OFF_BHI + bb + 16);
                uint32_t bl0 = *(const uint32_t*)(smc + OFF_BLO + bb);
                uint32_t bl1 = *(const uint32_t*)(smc + OFF_BLO + bb + 16);
#pragma unroll
                for (int mt = 0; mt < 2; mt++) {
                    mma16816(acc[mt][nt], ah[mt][0], ah[mt][1], ah[mt][2], ah[mt][3], bh0, bh1);
                    mma16816(acc[mt][nt], ah[mt][0], ah[mt][1], ah[mt][2], ah[mt][3], bl0, bl1);
                    mma16816(acc[mt][nt], al[mt][0], al[mt][1], al[mt][2], al[mt][3], bh0, bh1);
                }
            }
        }
    }

    // ---- epilogue: write C + group-norm stat partials ----
    float lsum = 0.f, lss = 0.f;
    float* statp = TR ? g_stat2 : g_stat1;
#pragma unroll
    for (int mt = 0; mt < 2; mt++) {
        int m = m0 + warp_m * 32 + mt * 16 + g;
#pragma unroll
        for (int nt = 0; nt < 8; nt++) {
            float c0 = acc[mt][nt][0], c1 = acc[mt][nt][1];
            float c2 = acc[mt][nt][2], c3 = acc[mt][nt][3];
            int sc = s0 + warp_n * 64 + nt * 8 + t * 2;
            if (!TR) {
                g_Y1[((size_t)n * HW + sc)     * HIDC + m]     = c0;
                g_Y1[((size_t)n * HW + sc + 1) * HIDC + m]     = c1;
                g_Y1[((size_t)n * HW + sc)     * HIDC + m + 8] = c2;
                g_Y1[((size_t)n * HW + sc + 1) * HIDC + m + 8] = c3;
            } else {
                float2 p01 = make_float2(c0, c1);
                float2 p23 = make_float2(c2, c3);
                *(float2*)&g_Y2[((size_t)n * COUT + m)     * HW + sc] = p01;
                *(float2*)&g_Y2[((size_t)n * COUT + m + 8) * HW + sc] = p23;
            }
            lsum += c0 + c1 + c2 + c3;
            lss  += c0 * c0 + c1 * c1 + c2 * c2 + c3 * c3;
        }
    }
#pragma unroll
    for (int o = 16; o > 0; o >>= 1) {
        lsum += __shfl_xor_sync(0xffffffffu, lsum, o);
        lss  += __shfl_xor_sync(0xffffffffu, lss, o);
    }
    if (lane == 0) {
        int grp = (m0 + warp_m * 32) >> (TR ? 5 : 6);
        atomicAdd(&statp[((size_t)n * 8 + grp) * 2],     lsum);
        atomicAdd(&statp[((size_t)n * 8 + grp) * 2 + 1], lss);
    }
}

// ---------------- finalize GN1 -> per-channel scale/shift ----------------
__global__ void finalize1_kernel(const float* __restrict__ e_g1,
                                 const float* __restrict__ e_b1) {
    int n = blockIdx.x;
    int c = threadIdx.x;           // 0..511
    if (g_w[n] == 0.f) {
        g_scale1[n * HIDC + c] = 0.f;
        g_shift1[n * HIDC + c] = 0.f;
        return;
    }
    int e = g_eidx[n];
    int g = c >> 6;
    float cnt = 64.f * 4096.f;
    float s  = g_stat1[(n * 8 + g) * 2];
    float ss = g_stat1[(n * 8 + g) * 2 + 1];
    float mean = s / cnt;
    float var  = ss / cnt - mean * mean;
    float inv  = rsqrtf(var + 1e-5f);
    float gm = e_g1[e * HIDC + c], bt = e_b1[e * HIDC + c];
    g_scale1[n * HIDC + c] = inv * gm;
    g_shift1[n * HIDC + c] = bt - mean * inv * gm;
}

// ---------------- finalize GN2 (+ routing weight) ----------------
__global__ void finalize2_kernel(const float* __restrict__ e_g2,
                                 const float* __restrict__ e_b2) {
    int n = blockIdx.x;
    int c = threadIdx.x;           // 0..255
    float w = g_w[n];
    if (w == 0.f) {
        g_scale2[n * COUT + c] = 0.f;
        g_shift2[n * COUT + c] = 0.f;
        return;
    }
    int e = g_eidx[n];
    int g = c >> 5;
    float cnt = 32.f * 4096.f;
    float s  = g_stat2[(n * 8 + g) * 2];
    float ss = g_stat2[(n * 8 + g) * 2 + 1];
    float mean = s / cnt;
    float var  = ss / cnt - mean * mean;
    float inv  = rsqrtf(var + 1e-5f);
    float gm = e_g2[e * COUT + c], bt = e_b2[e * COUT + c];
    g_scale2[n * COUT + c] = w * inv * gm;
    g_shift2[n * COUT + c] = w * (bt - mean * inv * gm);
}

// ---------------- combine ----------------
__global__ void combine_kernel(float* __restrict__ out) {
    size_t i = (size_t)blockIdx.x * 256 + threadIdx.x;   // float4 units
    if (i >= (size_t)B_IMG * COUT * (HW / 4)) return;
    int p4 = (int)(i & 1023);
    int c  = (int)((i >> 10) & 255);
    int b  = (int)(i >> 18);
    int n0 = 2 * b;
    float S0 = g_scale2[n0 * COUT + c],       T0 = g_shift2[n0 * COUT + c];
    float S1 = g_scale2[(n0 + 1) * COUT + c], T1 = g_shift2[(n0 + 1) * COUT + c];
    const float4 y0 = *(const float4*)&g_Y2[((size_t)n0 * COUT + c) * HW + p4 * 4];
    const float4 y1 = *(const float4*)&g_Y2[((size_t)(n0 + 1) * COUT + c) * HW + p4 * 4];
    float T = T0 + T1;
    float4 o;
    o.x = y0.x * S0 + y1.x * S1 + T;
    o.y = y0.y * S0 + y1.y * S1 + T;
    o.z = y0.z * S0 + y1.z * S1 + T;
    o.w = y0.w * S0 + y1.w * S1 + T;
    *(float4*)&out[i * 4] = o;
}

// ---------------- launch ----------------
extern "C" void kernel_launch(void* const* d_in, const int* in_sizes, int n_in,
                              void* d_out, int out_size) {
    const float* x     = (const float*)d_in[0];
    const float* r_dw  = (const float*)d_in[1];
    const float* r_g1  = (const float*)d_in[2];
    const float* r_b1  = (const float*)d_in[3];
    const float* r_pw1 = (const float*)d_in[4];
    const float* r_g2  = (const float*)d_in[5];
    const float* r_b2  = (const float*)d_in[6];
    const float* r_pw2 = (const float*)d_in[7];
    const float* r_pb2 = (const float*)d_in[8];
    const float* e_w1  = (const float*)d_in[9];
    const float* e_g1  = (const float*)d_in[10];
    const float* e_b1  = (const float*)d_in[11];
    const float* e_w2  = (const float*)d_in[12];
    const float* e_g2  = (const float*)d_in[13];
    const float* e_b2  = (const float*)d_in[14];
    float* out = (float*)d_out;

    const int router_smem = ROUTER_SMEM_FLOATS * (int)sizeof(float);
    cudaFuncSetAttribute(router_kernel, cudaFuncAttributeMaxDynamicSharedMemorySize, router_smem);
    cudaFuncSetAttribute(hmma_gemm_kernel<false>, cudaFuncAttributeMaxDynamicSharedMemorySize, GEMM_SMEM);
    cudaFuncSetAttribute(hmma_gemm_kernel<true>,  cudaFuncAttributeMaxDynamicSharedMemorySize, GEMM_SMEM);

    zero_stats_kernel<<<1, 1024>>>();
    {
        int tot = NEXP * HIDC * CIN + NEXP * COUT * HIDC;
        preconv_kernel<<<(tot + 255) / 256, 256>>>(e_w1, e_w2);
    }
    transpose_kernel<<<dim3(HW / 32, CIN / 32, B_IMG), dim3(32, 8)>>>(x);
    pool_kernel<<<B_IMG * CIN, 256>>>(x);
    router_kernel<<<B_IMG, 256, router_smem>>>(r_dw, r_g1, r_b1, r_pw1, r_g2, r_b2, r_pw2, r_pb2);
    hmma_gemm_kernel<false><<<dim3(HW / 128, HIDC / 128, NSLOT), 256, GEMM_SMEM>>>();
    finalize1_kernel<<<NSLOT, HIDC>>>(e_g1, e_b1);
    hmma_gemm_kernel<true><<<dim3(HW / 128, COUT / 128, NSLOT), 256, GEMM_SMEM>>>();
    finalize2_kernel<<<NSLOT, COUT>>>(e_g2, e_b2);
    combine_kernel<<<(B_IMG * COUT * (HW / 4) + 255) / 256, 256>>>(out);
}